// round 9
// baseline (speedup 1.0000x reference)
#include <cuda_runtime.h>
#include <math.h>

#define BATCH 16384
#define NUM_CLASSES 1604
#define C4 (NUM_CLASSES / 4)      // 401 float4 per row
#define THREADS 256
#define WARPS 8
#define EPS 1e-6f

// Device-global scratch (allocation-free). g_counts starts zeroed (static
// init) and is re-zeroed by scatter_kernel each launch, so every graph
// replay sees the same initial state.
__device__ int g_counts[NUM_CLASSES];          // zero-initialized
__device__ int g_off[NUM_CLASSES + 1];
__device__ int g_cursor[NUM_CLASSES];
__device__ int g_order[BATCH];

// ---------------- pass 1: histogram of targets ----------------
__global__ void hist_kernel(const int* __restrict__ targets) {
    int b = blockIdx.x * blockDim.x + threadIdx.x;
    if (b < BATCH) atomicAdd(&g_counts[targets[b]], 1);
}

// ---------------- pass 2: exclusive scan (1 block, 512 thr, 4 elem/thr) ---
// Also zeroes the scalar output (runs before the main kernel's atomics).
__global__ void scan_kernel(float* out) {
    const int t = threadIdx.x;            // 0..511, covers 2048 >= 1605
    const int lane = t & 31, wid = t >> 5;
    const int base = t * 4;
    if (t == 0) out[0] = 0.0f;

    int c[4];
    #pragma unroll
    for (int j = 0; j < 4; j++)
        c[j] = (base + j < NUM_CLASSES) ? g_counts[base + j] : 0;
    int local = c[0] + c[1] + c[2] + c[3];

    int v = local;                        // inclusive warp scan
    #pragma unroll
    for (int o = 1; o < 32; o <<= 1) {
        int n = __shfl_up_sync(0xFFFFFFFFu, v, o);
        if (lane >= o) v += n;
    }
    __shared__ int wsum[16];
    if (lane == 31) wsum[wid] = v;
    __syncthreads();
    if (wid == 0) {
        int w = (lane < 16) ? wsum[lane] : 0;
        #pragma unroll
        for (int o = 1; o < 16; o <<= 1) {
            int n = __shfl_up_sync(0xFFFFFFFFu, w, o);
            if (lane >= o) w += n;
        }
        if (lane < 16) wsum[lane] = w;    // inclusive warp totals
    }
    __syncthreads();
    int warp_excl = (wid > 0) ? wsum[wid - 1] : 0;
    int run = warp_excl + (v - local);    // exclusive prefix for this chunk
    #pragma unroll
    for (int j = 0; j < 4; j++) {
        int idx = base + j;
        if (idx <= NUM_CLASSES) g_off[idx] = run;   // includes off[C] = BATCH
        if (idx <  NUM_CLASSES) g_cursor[idx] = run;
        run += c[j];
    }
}

// ---------------- pass 3: scatter sample ids; re-zero counts ----------------
__global__ void scatter_kernel(const int* __restrict__ targets) {
    int b = blockIdx.x * blockDim.x + threadIdx.x;
    if (b < BATCH) {
        int t = targets[b];
        int pos = atomicAdd(&g_cursor[t], 1);
        g_order[pos] = b;
    }
    // counts were consumed by scan; restore the all-zero invariant for the
    // next graph replay. Safe: no later kernel reads g_counts.
    if (b < NUM_CLASSES) g_counts[b] = 0;
}

// ---------------- pass 4: main loss, one block per class ----------------
// s[c] row lives in SMEM: the ~10.2 samples/class re-read it from smem,
// removing ~105 MB of L2/LTS traffic vs. the per-sample global gather.
// No max-subtraction: sigma is shift-invariant; EPS perturbation ~1e-7 rel
// (measured margin: rel_err ~4e-7 vs the 1e-3 gate).
__global__ __launch_bounds__(THREADS, 8)
void seesaw_main_kernel(const float* __restrict__ logits,
                        const float* __restrict__ s,
                        float* __restrict__ out) {
    const int c = blockIdx.x;
    const int off = g_off[c];
    const int cnt = g_off[c + 1] - off;
    if (cnt == 0) return;                 // uniform branch: whole block exits

    __shared__ float s_sm[NUM_CLASSES];
    __shared__ float sh_loss[WARPS];
    const int tid = threadIdx.x;
    const int warp = tid >> 5;
    const int lane = tid & 31;

    {   // cooperative s-row load (float4, fully coalesced, 2 iters/thread)
        const float4* __restrict__ srow =
            reinterpret_cast<const float4*>(s + (size_t)c * NUM_CLASSES);
        float4* s4w = reinterpret_cast<float4*>(s_sm);
        for (int i = tid; i < C4; i += THREADS) s4w[i] = srow[i];
    }
    __syncthreads();

    const float4* s4 = reinterpret_cast<const float4*>(s_sm);
    float wloss = 0.0f;

    for (int k = warp; k < cnt; k += WARPS) {
        const int b = g_order[off + k];
        const float4* __restrict__ lrow =
            reinterpret_cast<const float4*>(logits + (size_t)b * NUM_CLASSES);

        // denom = sum_j s[c,j]*exp(x_j); j==t term equals num_t (s[c,c]==1).
        float sum = 0.0f;
        #pragma unroll 4
        for (int i = lane; i < C4; i += 32) {
            float4 x = lrow[i];
            float4 w = s4[i];
            sum += w.x * __expf(x.x) + w.y * __expf(x.y)
                 + w.z * __expf(x.z) + w.w * __expf(x.w);
        }
        #pragma unroll
        for (int o = 16; o > 0; o >>= 1)
            sum += __shfl_xor_sync(0xFFFFFFFFu, sum, o);

        if (lane == 0) {
            float xt = logits[(size_t)b * NUM_CLASSES + c];
            float num_t = __expf(xt);
            float sigma = num_t / (sum + EPS);
            wloss += -__logf(sigma + EPS);
        }
    }

    if (lane == 0) sh_loss[warp] = wloss;   // every warp writes (0 if no work)
    __syncthreads();
    if (tid == 0) {
        float acc = 0.0f;
        #pragma unroll
        for (int w = 0; w < WARPS; w++) acc += sh_loss[w];
        atomicAdd(out, acc * (1.0f / (float)BATCH));
    }
}

extern "C" void kernel_launch(void* const* d_in, const int* in_sizes, int n_in,
                              void* d_out, int out_size) {
    const float* logits  = (const float*)d_in[0];
    const float* s       = (const float*)d_in[1];
    const int*   targets = (const int*)d_in[2];
    float* out = (float*)d_out;

    hist_kernel   <<<BATCH / 256, 256>>>(targets);
    scan_kernel   <<<1, 512>>>(out);
    scatter_kernel<<<BATCH / 256, 256>>>(targets);
    seesaw_main_kernel<<<NUM_CLASSES, THREADS>>>(logits, s, out);
}

// round 13
// speedup vs baseline: 1.4210x; 1.4210x over previous
#include <cuda_runtime.h>
#include <math.h>

#define BATCH 16384
#define NUM_CLASSES 1604
#define C4 (NUM_CLASSES / 4)      // 401 float4 per row
#define WARPS_PER_BLOCK 8
#define THREADS (WARPS_PER_BLOCK * 32)
#define EPS 1e-6f

// Device-global scratch (allocation-free). g_counts starts zeroed (static
// init) and is re-zeroed by scatter_kernel each launch -> every graph
// replay sees the same initial state.
__device__ int g_counts[NUM_CLASSES];          // zero-initialized
__device__ int g_off[NUM_CLASSES];
__device__ int g_order[BATCH];                 // packed: b | (t << 14)

// ---------------- pass 1: histogram of targets ----------------
__global__ void hist_kernel(const int* __restrict__ targets) {
    int b = blockIdx.x * blockDim.x + threadIdx.x;
    if (b < BATCH) atomicAdd(&g_counts[targets[b]], 1);
}

// ---------------- pass 2: exclusive scan (1 block, 512 thr, 4 elem/thr) ---
// Also zeroes the scalar output (runs before the main kernel's atomics).
__global__ void scan_kernel(float* out) {
    const int t = threadIdx.x;            // 0..511, covers 2048 >= 1604
    const int lane = t & 31, wid = t >> 5;
    const int base = t * 4;
    if (t == 0) out[0] = 0.0f;

    int c[4];
    #pragma unroll
    for (int j = 0; j < 4; j++)
        c[j] = (base + j < NUM_CLASSES) ? g_counts[base + j] : 0;
    int local = c[0] + c[1] + c[2] + c[3];

    int v = local;                        // inclusive warp scan
    #pragma unroll
    for (int o = 1; o < 32; o <<= 1) {
        int n = __shfl_up_sync(0xFFFFFFFFu, v, o);
        if (lane >= o) v += n;
    }
    __shared__ int wsum[16];
    if (lane == 31) wsum[wid] = v;
    __syncthreads();
    if (wid == 0) {
        int w = (lane < 16) ? wsum[lane] : 0;
        #pragma unroll
        for (int o = 1; o < 16; o <<= 1) {
            int n = __shfl_up_sync(0xFFFFFFFFu, w, o);
            if (lane >= o) w += n;
        }
        if (lane < 16) wsum[lane] = w;    // inclusive warp totals
    }
    __syncthreads();
    int warp_excl = (wid > 0) ? wsum[wid - 1] : 0;
    int run = warp_excl + (v - local);    // exclusive prefix for this chunk
    #pragma unroll
    for (int j = 0; j < 4; j++) {
        int idx = base + j;
        if (idx < NUM_CLASSES) g_off[idx] = run;   // doubles as scatter cursor
        run += c[j];
    }
}

// ---------------- pass 3: scatter packed (b,t) ids; re-zero counts ---------
__global__ void scatter_kernel(const int* __restrict__ targets) {
    int b = blockIdx.x * blockDim.x + threadIdx.x;
    if (b < BATCH) {
        int t = targets[b];
        int pos = atomicAdd(&g_off[t], 1);         // g_off consumed as cursor
        g_order[pos] = b | (t << 14);              // b < 16384, t < 2048
    }
    // restore the all-zero invariant for the next graph replay
    if (b < NUM_CLASSES) g_counts[b] = 0;
}

// ---------------- pass 4: main loss ----------------
// One warp per SORTED sample: block k owns sorted samples [8k, 8k+8), which
// mostly share one class. The block's 8 warps stream the SAME 6.4KB s row in
// lockstep -> first-toucher misses to L2, the rest hit per-SM L1, removing
// ~7/8 of the s-row LTS traffic with perfectly uniform work (no imbalance,
// exact 2048-block R5 schedule).
// No max-subtraction: sigma is shift-invariant; EPS perturbation ~1e-7 rel
// (measured margin: rel_err ~5e-7 vs the 1e-3 gate).
__global__ __launch_bounds__(THREADS, 8)
void seesaw_main_kernel(const float* __restrict__ logits,
                        const float* __restrict__ s,
                        float* __restrict__ out) {
    const int warp = threadIdx.x >> 5;
    const int lane = threadIdx.x & 31;
    const int packed = g_order[blockIdx.x * WARPS_PER_BLOCK + warp];
    const int b = packed & 0x3FFF;
    const int t = packed >> 14;

    const float4* __restrict__ lrow =
        reinterpret_cast<const float4*>(logits + (size_t)b * NUM_CLASSES);
    const float4* __restrict__ srow =
        reinterpret_cast<const float4*>(s + (size_t)t * NUM_CLASSES);

    // denom = sum_j s[t,j] * exp(x_j); the j==t term equals num_t (s[t,t]==1).
    float sum = 0.0f;
    #pragma unroll 4
    for (int i = lane; i < C4; i += 32) {
        float4 x = lrow[i];
        float4 w = srow[i];
        sum += w.x * __expf(x.x) + w.y * __expf(x.y)
             + w.z * __expf(x.z) + w.w * __expf(x.w);
    }

    #pragma unroll
    for (int o = 16; o > 0; o >>= 1)
        sum += __shfl_xor_sync(0xFFFFFFFFu, sum, o);

    __shared__ float sh_loss[WARPS_PER_BLOCK];
    if (lane == 0) {
        float xt = logits[(size_t)b * NUM_CLASSES + t];
        float num_t = __expf(xt);
        float sigma = num_t / (sum + EPS);
        sh_loss[warp] = -__logf(sigma + EPS);
    }
    __syncthreads();

    if (threadIdx.x == 0) {
        float acc = 0.0f;
        #pragma unroll
        for (int w = 0; w < WARPS_PER_BLOCK; w++) acc += sh_loss[w];
        atomicAdd(out, acc * (1.0f / (float)BATCH));
    }
}

extern "C" void kernel_launch(void* const* d_in, const int* in_sizes, int n_in,
                              void* d_out, int out_size) {
    const float* logits  = (const float*)d_in[0];
    const float* s       = (const float*)d_in[1];
    const int*   targets = (const int*)d_in[2];
    float* out = (float*)d_out;

    hist_kernel   <<<BATCH / 256, 256>>>(targets);
    scan_kernel   <<<1, 512>>>(out);
    scatter_kernel<<<BATCH / 256, 256>>>(targets);
    seesaw_main_kernel<<<BATCH / WARPS_PER_BLOCK, THREADS>>>(logits, s, out);
}

// round 15
// speedup vs baseline: 1.5138x; 1.0653x over previous
#include <cuda_runtime.h>
#include <math.h>

#define BATCH 16384
#define NUM_CLASSES 1604
#define C4 (NUM_CLASSES / 4)      // 401 float4 per row
#define WARPS_PER_BLOCK 8
#define THREADS (WARPS_PER_BLOCK * 32)
#define EPS 1e-6f

__global__ void zero_out_kernel(float* out) {
    if (threadIdx.x == 0) out[0] = 0.0f;
}

// Predicated paired load: past the row end return w=0 (zero contribution),
// so the pipeline needs no tail code and all lanes run the same trip count.
__device__ __forceinline__ void ldp(const float4* __restrict__ lrow,
                                    const float4* __restrict__ srow,
                                    int i, float4& x, float4& w) {
    if (i < C4) { x = lrow[i]; w = srow[i]; }
    else        { x = make_float4(0.f, 0.f, 0.f, 0.f);
                  w = make_float4(0.f, 0.f, 0.f, 0.f); }
}

__device__ __forceinline__ float wexp4(const float4& w, const float4& x) {
    return w.x * __expf(x.x) + w.y * __expf(x.y)
         + w.z * __expf(x.z) + w.w * __expf(x.w);
}

// One warp per sample. No max-subtraction (sigma is shift-invariant; EPS
// perturbation ~1e-7 relative; measured margin 2.5e-7 vs 1e-3 gate).
// Explicit 2-deep x 2-wide software pipeline: loads for steps k+2,k+3 issue
// BEFORE the expf/FFMA work of steps k,k+1 -> steady-state MLP 4-8 LDG.128
// per warp instead of the compiler's ~2. occ target 6 blocks/SM (42 regs)
// funds the pipeline buffers (6 float4 = 24 regs) without R6's occ collapse.
__global__ __launch_bounds__(THREADS, 6)
void seesaw_loss_kernel(const float* __restrict__ logits,
                        const float* __restrict__ s,
                        const int* __restrict__ targets,
                        float* __restrict__ out) {
    const int warp = threadIdx.x >> 5;
    const int lane = threadIdx.x & 31;
    const int b = blockIdx.x * WARPS_PER_BLOCK + warp;
    const int t = targets[b];

    const float4* __restrict__ lrow =
        reinterpret_cast<const float4*>(logits + (size_t)b * NUM_CLASSES);
    const float4* __restrict__ srow =
        reinterpret_cast<const float4*>(s + (size_t)t * NUM_CLASSES);

    // denom = sum_j s[t,j]*exp(x_j); the j==t term equals num_t (s[t,t]==1).
    float4 xa, wa, xb, wb;
    ldp(lrow, srow, lane,      xa, wa);   // step 0
    ldp(lrow, srow, lane + 32, xb, wb);   // step 1

    float s0 = 0.0f, s1 = 0.0f;

    // 13 strided steps per lane (ceil(401/32)); rounds of 2 with prefetch 2
    // ahead. Steps 13..15 are fully predicated-out (w=0).
    #pragma unroll 1
    for (int k = 0; k < 13; k += 2) {
        float4 xn, wn;
        ldp(lrow, srow, lane + (k + 2) * 32, xn, wn);   // prefetch k+2
        s0 += wexp4(wa, xa);                            // consume k
        xa = xn; wa = wn;
        ldp(lrow, srow, lane + (k + 3) * 32, xn, wn);   // prefetch k+3
        s1 += wexp4(wb, xb);                            // consume k+1
        xb = xn; wb = wn;
    }

    float sum = s0 + s1;

    // Warp sum.
    #pragma unroll
    for (int o = 16; o > 0; o >>= 1)
        sum += __shfl_xor_sync(0xFFFFFFFFu, sum, o);

    __shared__ float sh_loss[WARPS_PER_BLOCK];
    if (lane == 0) {
        float xt = logits[(size_t)b * NUM_CLASSES + t];
        float num_t = __expf(xt);
        float sigma = num_t / (sum + EPS);
        sh_loss[warp] = -__logf(sigma + EPS);
    }
    __syncthreads();

    if (threadIdx.x == 0) {
        float acc = 0.0f;
        #pragma unroll
        for (int w = 0; w < WARPS_PER_BLOCK; w++) acc += sh_loss[w];
        atomicAdd(out, acc * (1.0f / (float)BATCH));
    }
}

extern "C" void kernel_launch(void* const* d_in, const int* in_sizes, int n_in,
                              void* d_out, int out_size) {
    const float* logits  = (const float*)d_in[0];
    const float* s       = (const float*)d_in[1];
    const int*   targets = (const int*)d_in[2];
    float* out = (float*)d_out;

    zero_out_kernel<<<1, 32>>>(out);
    seesaw_loss_kernel<<<BATCH / WARPS_PER_BLOCK, THREADS>>>(logits, s, targets, out);
}